// round 1
// baseline (speedup 1.0000x reference)
#include <cuda_runtime.h>

// DetectionLoss: SSD-style loss with hard-negative mining.
// Phase A: per-anchor IoU/BCE (only obj channel read for all anchors; box/cls
//          channels read only for sparse positives). Writes BCE of negatives
//          to scratch, accumulates per-(image,scale) stats.
// Phase B: per-(image,scale) radix-select of top-nneg negative BCE, combine.
// Phase C: final 4-float output.

#define IMGF 224.0f
#define NG 16
#define NBATCH 64

static const int   NA0 = 3 * 112 * 112;   // 37632
static const int   NA1 = 3 * 56 * 56;     // 9408
static const int   NA2 = 3 * 28 * 28;     // 2352
// scratch layout: [scale][image][anchor]
// off0 = 0, off1 = 64*37632 = 2408448, off2 = 2408448+64*9408 = 3010560
static __device__ float g_bce[3161088];

static __device__ float g_posbce[192];
static __device__ float g_cls[192];
static __device__ float g_loc[192];
static __device__ int   g_npos[192];
static __device__ int   g_navail[192];
static __device__ float g_tot[3];

__global__ void k_init() {
    int t = blockIdx.x * blockDim.x + threadIdx.x;
    if (t < 192) {
        g_posbce[t] = 0.f; g_cls[t] = 0.f; g_loc[t] = 0.f;
        g_npos[t] = 0; g_navail[t] = 0;
    }
    if (t < 3) g_tot[t] = 0.f;
}

__device__ __forceinline__ unsigned f2key(float f) {
    unsigned u = __float_as_uint(f);
    return u ^ (((unsigned)((int)u >> 31)) | 0x80000000u);
}
__device__ __forceinline__ float key2f(unsigned u) {
    unsigned b = (u & 0x80000000u) ? (u ^ 0x80000000u) : ~u;
    return __uint_as_float(b);
}

__global__ void k_phaseA(const float* __restrict__ p,
                         const float* __restrict__ anchors,
                         const float* __restrict__ tboxes,
                         const int*   __restrict__ tlabels,
                         int H, int Na, int accBase, long scrBase)
{
    const int b = blockIdx.y;
    __shared__ float stb[NG * 4];
    __shared__ int   stl[NG];
    __shared__ float s_pb, s_cl, s_lo;
    __shared__ int   s_np, s_nv;

    const int t = threadIdx.x;
    if (t < NG * 4) stb[t] = tboxes[b * NG * 4 + t] / IMGF;
    if (t < NG)     stl[t] = tlabels[b * NG + t];
    if (t == 0) { s_pb = 0.f; s_cl = 0.f; s_lo = 0.f; s_np = 0; s_nv = 0; }
    __syncthreads();

    const int n = blockIdx.x * blockDim.x + t;
    if (n < Na) {
        const int HH = H * H;
        const float ax1 = anchors[n * 4 + 0] / IMGF;
        const float ay1 = anchors[n * 4 + 1] / IMGF;
        const float ax2 = anchors[n * 4 + 2] / IMGF;
        const float ay2 = anchors[n * 4 + 3] / IMGF;
        const float aw = ax2 - ax1, ah = ay2 - ay1;
        const float area_a = aw * ah;

        float best = -1.0f; int bi = 0;
        #pragma unroll
        for (int g = 0; g < NG; g++) {
            float bx1 = stb[g * 4 + 0], by1 = stb[g * 4 + 1];
            float bx2 = stb[g * 4 + 2], by2 = stb[g * 4 + 3];
            float lx = fmaxf(ax1, bx1), ly = fmaxf(ay1, by1);
            float rx = fminf(ax2, bx2), ry = fminf(ay2, by2);
            float iw = fmaxf(rx - lx, 0.f), ih = fmaxf(ry - ly, 0.f);
            float inter = iw * ih;
            float ab = (bx2 - bx1) * (by2 - by1);
            float iou = inter / (area_a + ab - inter + 1e-9f);
            if (iou > best) { best = iou; bi = g; }
        }
        const bool pos = best >= 0.5f;
        const bool neg = best < 0.4f;

        const int a = n / HH;
        const int rem = n - a * HH;
        const float* base = p + (((long)b * 3 + a) * 8) * (long)HH + rem;

        const float o = base[(long)4 * HH];          // objectness channel
        const float objt = pos ? 1.f : 0.f;
        const float bce = fmaxf(o, 0.f) - o * objt + log1pf(expf(-fabsf(o)));

        g_bce[scrBase + (long)b * Na + n] = neg ? bce : -1.0f;

        if (neg) atomicAdd(&s_nv, 1);
        if (pos) {
            atomicAdd(&s_np, 1);
            atomicAdd(&s_pb, bce);
            // localization target encoding
            float mx1 = stb[bi * 4 + 0], my1 = stb[bi * 4 + 1];
            float mx2 = stb[bi * 4 + 2], my2 = stb[bi * 4 + 3];
            float gcx = 0.5f * (mx1 + mx2), gcy = 0.5f * (my1 + my2);
            float gw = mx2 - mx1, gh = my2 - my1;
            float acx = 0.5f * (ax1 + ax2), acy = 0.5f * (ay1 + ay2);
            float e0 = (gcx - acx) / aw;
            float e1 = (gcy - acy) / ah;
            float e2 = logf(gw / aw + 1e-6f);
            float e3 = logf(gh / ah + 1e-6f);
            float d0 = base[0]             - e0;
            float d1 = base[(long)1 * HH]  - e1;
            float d2 = base[(long)2 * HH]  - e2;
            float d3 = base[(long)3 * HH]  - e3;
            #define SL1_(d) (fabsf(d) < 1.f ? 0.5f * (d) * (d) : fabsf(d) - 0.5f)
            atomicAdd(&s_lo, SL1_(d0) + SL1_(d1) + SL1_(d2) + SL1_(d3));
            #undef SL1_
            // classification CE on positives
            float z0 = base[(long)5 * HH];
            float z1 = base[(long)6 * HH];
            float z2 = base[(long)7 * HH];
            float m = fmaxf(z0, fmaxf(z1, z2));
            float lse = m + logf(expf(z0 - m) + expf(z1 - m) + expf(z2 - m));
            int ml = stl[bi];
            float zl = (ml == 1) ? z0 : ((ml == 2) ? z1 : z2);
            atomicAdd(&s_cl, lse - zl);
        }
    }
    __syncthreads();
    if (t == 0) {
        const int acc = accBase + b;
        if (s_np) {
            atomicAdd(&g_npos[acc],   s_np);
            atomicAdd(&g_posbce[acc], s_pb);
            atomicAdd(&g_cls[acc],    s_cl);
            atomicAdd(&g_loc[acc],    s_lo);
        }
        if (s_nv) atomicAdd(&g_navail[acc], s_nv);
    }
}

// One block per (scale, image): radix-select k-th largest BCE among negatives.
__global__ void k_phaseB()
{
    const int Na_tab[3]  = { NA0, NA1, NA2 };
    const long off_tab[3] = { 0L, 2408448L, 3010560L };

    const int idx = blockIdx.x;          // 0..191
    const int scale = idx >> 6;
    const int b = idx & 63;
    const int Na = Na_tab[scale];
    const long base = off_tab[scale] + (long)b * Na;
    const int npos = g_npos[idx];
    const int navail = g_navail[idx];
    const int t = threadIdx.x;

    __shared__ unsigned hist[256];
    __shared__ int s_sel, s_kr;
    __shared__ float s_sum[256];

    float o = 0.f, c = 0.f, l = 0.f;

    if (npos > 0 && navail > 0) {
        const int k = min(3 * npos, navail);
        unsigned prefix = 0;
        int kr = k;
        for (int shift = 24; shift >= 0; shift -= 8) {
            hist[t] = 0;
            __syncthreads();
            const unsigned pmask = (shift == 24) ? 0u : (0xFFFFFFFFu << (shift + 8));
            for (int i = t; i < Na; i += 256) {
                unsigned u = f2key(g_bce[base + i]);
                if ((u & pmask) == prefix)
                    atomicAdd(&hist[(u >> shift) & 0xFFu], 1u);
            }
            __syncthreads();
            if (t == 0) {
                int accum = 0, sel = 0, krem = kr;
                for (int bkt = 255; bkt >= 0; bkt--) {
                    int h = (int)hist[bkt];
                    if (accum + h >= kr) { sel = bkt; krem = kr - accum; break; }
                    accum += h;
                }
                s_sel = sel; s_kr = krem;
            }
            __syncthreads();
            prefix |= ((unsigned)s_sel) << shift;
            kr = s_kr;
            __syncthreads();
        }
        const unsigned thr_key = prefix;       // key of k-th largest
        const float thr = key2f(thr_key);
        float sum = 0.f;
        for (int i = t; i < Na; i += 256) {
            float v = g_bce[base + i];
            if (f2key(v) > thr_key) sum += v;
        }
        s_sum[t] = sum;
        __syncthreads();
        for (int s = 128; s > 0; s >>= 1) {
            if (t < s) s_sum[t] += s_sum[t + s];
            __syncthreads();
        }
        const float neg_sum = s_sum[0] + (float)kr * thr;
        o = g_posbce[idx] / (float)npos + neg_sum / (float)k;
    }
    if (npos > 0) {
        c = g_cls[idx] / (float)npos;
        l = g_loc[idx] / (4.0f * (float)npos);
    }
    if (t == 0) {
        atomicAdd(&g_tot[0], o);
        atomicAdd(&g_tot[1], c);
        atomicAdd(&g_tot[2], l);
    }
}

__global__ void k_final(float* out) {
    if (threadIdx.x == 0) {
        float o = g_tot[0] / (float)NBATCH;
        float c = g_tot[1] / (float)NBATCH;
        float l = g_tot[2] / (float)NBATCH;
        out[0] = o; out[1] = c; out[2] = l; out[3] = o + c + l;
    }
}

extern "C" void kernel_launch(void* const* d_in, const int* in_sizes, int n_in,
                              void* d_out, int out_size)
{
    const float* p0 = (const float*)d_in[0];
    const float* p1 = (const float*)d_in[1];
    const float* p2 = (const float*)d_in[2];
    const float* a0 = (const float*)d_in[3];
    const float* a1 = (const float*)d_in[4];
    const float* a2 = (const float*)d_in[5];
    const float* tb = (const float*)d_in[6];
    const int*   tl = (const int*)  d_in[7];

    k_init<<<1, 256>>>();

    dim3 g0((NA0 + 255) / 256, NBATCH);
    dim3 g1((NA1 + 255) / 256, NBATCH);
    dim3 g2((NA2 + 255) / 256, NBATCH);
    k_phaseA<<<g0, 256>>>(p0, a0, tb, tl, 112, NA0, 0,   0L);
    k_phaseA<<<g1, 256>>>(p1, a1, tb, tl, 56,  NA1, 64,  2408448L);
    k_phaseA<<<g2, 256>>>(p2, a2, tb, tl, 28,  NA2, 128, 3010560L);

    k_phaseB<<<192, 256>>>();
    k_final<<<1, 32>>>((float*)d_out);
}

// round 2
// speedup vs baseline: 1.5145x; 1.5145x over previous
#include <cuda_runtime.h>

#define IMGF 224.0f
#define NG 16
#define NBATCH 64

static const int NA0 = 3 * 112 * 112;   // 37632
static const int NA1 = 3 * 56 * 56;     // 9408
static const int NA2 = 3 * 28 * 28;     // 2352
static const int NB0 = 147;             // ceil(NA0/256)
static const int NB1 = 37;
static const int NB2 = 10;

// scratch: [scale][image][anchor]
static __device__ float g_bce[3161088];
// level-1 histograms: [img-scale idx][2048 bins of float-bits>>20]
static __device__ int   g_hist[192 * 2048];

static __device__ float g_posbce[192];
static __device__ float g_cls[192];
static __device__ float g_loc[192];
static __device__ int   g_npos[192];
static __device__ int   g_navail[192];
static __device__ float g_tot[3];

__global__ void __launch_bounds__(1024) k_init() {
    int t = blockIdx.x * 1024 + threadIdx.x;
    if (t < 192 * 2048) g_hist[t] = 0;
    if (t < 192) {
        g_posbce[t] = 0.f; g_cls[t] = 0.f; g_loc[t] = 0.f;
        g_npos[t] = 0; g_navail[t] = 0;
    }
    if (t < 3) g_tot[t] = 0.f;
}

// ---------------- Phase A ----------------

template<int H, int NA, int ACCB, long SCRB>
__device__ __forceinline__ void phaseA_impl(const float* __restrict__ p,
                                            const float* __restrict__ anchors,
                                            const float* __restrict__ tb,
                                            const int*   __restrict__ tl,
                                            int bs, int b)
{
    constexpr int HH = H * H;
    __shared__ float stb[NG * 4];
    __shared__ int   stl[NG];
    __shared__ float s_pb, s_cl, s_lo;
    __shared__ int   s_np, s_nv;

    const int t = threadIdx.x;
    if (t < NG * 4) stb[t] = tb[b * NG * 4 + t] / IMGF;
    if (t < NG)     stl[t] = tl[b * NG + t];
    if (t == 0) { s_pb = 0.f; s_cl = 0.f; s_lo = 0.f; s_np = 0; s_nv = 0; }
    __syncthreads();

    const int n = bs * 256 + t;
    const bool active = (n < NA);
    bool pos = false, neg = false;

    if (active) {
        const float4 a4 = ((const float4*)anchors)[n];
        const float ax1 = a4.x / IMGF, ay1 = a4.y / IMGF;
        const float ax2 = a4.z / IMGF, ay2 = a4.w / IMGF;
        const float aw = ax2 - ax1, ah = ay2 - ay1;
        const float area_a = aw * ah;

        float best = -1.0f; int bi = 0;
        #pragma unroll
        for (int g = 0; g < NG; g++) {
            float bx1 = stb[g * 4 + 0], by1 = stb[g * 4 + 1];
            float bx2 = stb[g * 4 + 2], by2 = stb[g * 4 + 3];
            float lx = fmaxf(ax1, bx1), ly = fmaxf(ay1, by1);
            float rx = fminf(ax2, bx2), ry = fminf(ay2, by2);
            float iw = fmaxf(rx - lx, 0.f), ih = fmaxf(ry - ly, 0.f);
            float inter = iw * ih;
            float ab = (bx2 - bx1) * (by2 - by1);
            float iou = inter / (area_a + ab - inter + 1e-9f);
            if (iou > best) { best = iou; bi = g; }
        }
        pos = best >= 0.5f;
        neg = best < 0.4f;

        const int a = n / HH;
        const int rem = n - a * HH;
        const float* base = p + (((long)b * 3 + a) * 8) * (long)HH + rem;

        const float o = base[(long)4 * HH];
        const float objt = pos ? 1.f : 0.f;
        const float bce = fmaxf(o, 0.f) - o * objt + log1pf(expf(-fabsf(o)));

        g_bce[SCRB + (long)b * NA + n] = neg ? bce : -1.0f;

        if (neg)
            atomicAdd(&g_hist[(ACCB + b) * 2048 + (int)(__float_as_uint(bce) >> 20)], 1);

        if (pos) {
            atomicAdd(&s_pb, bce);
            float mx1 = stb[bi * 4 + 0], my1 = stb[bi * 4 + 1];
            float mx2 = stb[bi * 4 + 2], my2 = stb[bi * 4 + 3];
            float gcx = 0.5f * (mx1 + mx2), gcy = 0.5f * (my1 + my2);
            float gw = mx2 - mx1, gh = my2 - my1;
            float acx = 0.5f * (ax1 + ax2), acy = 0.5f * (ay1 + ay2);
            float e0 = (gcx - acx) / aw;
            float e1 = (gcy - acy) / ah;
            float e2 = logf(gw / aw + 1e-6f);
            float e3 = logf(gh / ah + 1e-6f);
            float d0 = base[0]            - e0;
            float d1 = base[(long)1 * HH] - e1;
            float d2 = base[(long)2 * HH] - e2;
            float d3 = base[(long)3 * HH] - e3;
            #define SL1_(d) (fabsf(d) < 1.f ? 0.5f * (d) * (d) : fabsf(d) - 0.5f)
            atomicAdd(&s_lo, SL1_(d0) + SL1_(d1) + SL1_(d2) + SL1_(d3));
            #undef SL1_
            float z0 = base[(long)5 * HH];
            float z1 = base[(long)6 * HH];
            float z2 = base[(long)7 * HH];
            float m = fmaxf(z0, fmaxf(z1, z2));
            float lse = m + logf(expf(z0 - m) + expf(z1 - m) + expf(z2 - m));
            int ml = stl[bi];
            float zl = (ml == 1) ? z0 : ((ml == 2) ? z1 : z2);
            atomicAdd(&s_cl, lse - zl);
        }
    }

    // warp-aggregated counts
    unsigned nm = __ballot_sync(0xffffffff, neg);
    unsigned pm = __ballot_sync(0xffffffff, pos);
    if ((t & 31) == 0) {
        if (nm) atomicAdd(&s_nv, __popc(nm));
        if (pm) atomicAdd(&s_np, __popc(pm));
    }
    __syncthreads();
    if (t == 0) {
        const int acc = ACCB + b;
        if (s_np) {
            atomicAdd(&g_npos[acc],   s_np);
            atomicAdd(&g_posbce[acc], s_pb);
            atomicAdd(&g_cls[acc],    s_cl);
            atomicAdd(&g_loc[acc],    s_lo);
        }
        if (s_nv) atomicAdd(&g_navail[acc], s_nv);
    }
}

__global__ void __launch_bounds__(256) k_phaseA(const float* __restrict__ p0,
                                                const float* __restrict__ p1,
                                                const float* __restrict__ p2,
                                                const float* __restrict__ a0,
                                                const float* __restrict__ a1,
                                                const float* __restrict__ a2,
                                                const float* __restrict__ tb,
                                                const int*   __restrict__ tl)
{
    const int bx = blockIdx.x, b = blockIdx.y;
    if (bx < NB0)            phaseA_impl<112, NA0, 0,   0L>(p0, a0, tb, tl, bx, b);
    else if (bx < NB0 + NB1) phaseA_impl<56,  NA1, 64,  2408448L>(p1, a1, tb, tl, bx - NB0, b);
    else                     phaseA_impl<28,  NA2, 128, 3010560L>(p2, a2, tb, tl, bx - NB0 - NB1, b);
}

// ---------------- Phase B ----------------

__device__ __forceinline__ int incl_scan_1024(int* s_scan, int t, int v) {
    s_scan[t] = v;
    __syncthreads();
    #pragma unroll
    for (int off = 1; off < 1024; off <<= 1) {
        int u = (t >= off) ? s_scan[t - off] : 0;
        __syncthreads();
        s_scan[t] += u;
        __syncthreads();
    }
    return s_scan[t];
}

// select k-th from top over 1024 bins (bin order: 1023 .. 0)
__device__ __forceinline__ void select_top_1024(const int* hist, int* s_scan, int t,
                                                int k, int* sT, int* sKr) {
    int c = hist[1023 - t];
    int incl = incl_scan_1024(s_scan, t, c);
    int excl = incl - c;
    if (incl >= k && excl < k) { *sT = 1023 - t; *sKr = k - excl; }
    __syncthreads();
}

__global__ void __launch_bounds__(1024) k_phaseB()
{
    const int idx = blockIdx.x;                 // 0..191
    const int scale = idx >> 6;
    const int b = idx & 63;
    const int Na   = (scale == 0) ? NA0 : ((scale == 1) ? NA1 : NA2);
    const long off = ((scale == 0) ? 0L : ((scale == 1) ? 2408448L : 3010560L)) + (long)b * Na;
    const int t = threadIdx.x;
    const int npos = g_npos[idx];
    const int navail = g_navail[idx];

    __shared__ int   s_hist[2048];
    __shared__ int   s_scan[1024];
    __shared__ float s_buf[4096];
    __shared__ float s_fred[1024];
    __shared__ int   s_cnt, sT, sKr;

    float o = 0.f;

    if (npos > 0 && navail > 0) {
        const int k = min(3 * npos, navail);

        s_hist[t]        = g_hist[idx * 2048 + t];
        s_hist[t + 1024] = g_hist[idx * 2048 + t + 1024];
        if (t == 0) s_cnt = 0;
        __syncthreads();

        // level-1 select over 2048 bins (pairs from top)
        int c0 = s_hist[2047 - 2 * t];
        int c1 = s_hist[2046 - 2 * t];
        int incl = incl_scan_1024(s_scan, t, c0 + c1);
        int excl = incl - c0 - c1;
        if (incl >= k && excl < k) {
            if (excl + c0 >= k) { sT = 2047 - 2 * t; sKr = k - excl; }
            else                { sT = 2046 - 2 * t; sKr = k - excl - c0; }
        }
        __syncthreads();
        const int T = sT;
        int kr = sKr;
        const int cT = s_hist[T];
        __syncthreads();

        float sum = 0.f;
        unsigned thrbits;
        int krf;

        if (cT <= 4096) {
            // single data scan: sum above-bucket, gather bucket-T
            for (int i = t; i < Na; i += 1024) {
                float v = g_bce[off + i];
                unsigned u = __float_as_uint(v);
                if ((int)u >= 0) {
                    int bkt = (int)(u >> 20);
                    if (bkt > T) sum += v;
                    else if (bkt == T) { int pb = atomicAdd(&s_cnt, 1); s_buf[pb] = v; }
                }
            }
            __syncthreads();
            // level-2: bits[19:10] over buffer
            s_hist[t] = 0;
            __syncthreads();
            for (int i = t; i < cT; i += 1024)
                atomicAdd(&s_hist[(__float_as_uint(s_buf[i]) >> 10) & 1023], 1);
            __syncthreads();
            select_top_1024(s_hist, s_scan, t, kr, &sT, &sKr);
            const int T2 = sT; kr = sKr;
            __syncthreads();
            // level-3: bits[9:0]
            s_hist[t] = 0;
            __syncthreads();
            for (int i = t; i < cT; i += 1024) {
                unsigned u = __float_as_uint(s_buf[i]);
                if (((u >> 10) & 1023) == (unsigned)T2) atomicAdd(&s_hist[u & 1023], 1);
            }
            __syncthreads();
            select_top_1024(s_hist, s_scan, t, kr, &sT, &sKr);
            const int T3 = sT; krf = sKr;
            __syncthreads();
            thrbits = ((unsigned)T << 20) | ((unsigned)T2 << 10) | (unsigned)T3;
            for (int i = t; i < cT; i += 1024) {
                float v = s_buf[i];
                if (__float_as_uint(v) > thrbits) sum += v;
            }
        } else {
            // fallback: refine over global scratch (rare)
            s_hist[t] = 0;
            __syncthreads();
            for (int i = t; i < Na; i += 1024) {
                unsigned u = __float_as_uint(g_bce[off + i]);
                if ((int)u >= 0 && (u >> 20) == (unsigned)T)
                    atomicAdd(&s_hist[(u >> 10) & 1023], 1);
            }
            __syncthreads();
            select_top_1024(s_hist, s_scan, t, kr, &sT, &sKr);
            const int T2 = sT; kr = sKr;
            __syncthreads();
            s_hist[t] = 0;
            __syncthreads();
            const unsigned top22 = ((unsigned)T << 10) | (unsigned)T2;
            for (int i = t; i < Na; i += 1024) {
                unsigned u = __float_as_uint(g_bce[off + i]);
                if ((int)u >= 0 && (u >> 10) == top22)
                    atomicAdd(&s_hist[u & 1023], 1);
            }
            __syncthreads();
            select_top_1024(s_hist, s_scan, t, kr, &sT, &sKr);
            const int T3 = sT; krf = sKr;
            __syncthreads();
            thrbits = ((unsigned)T << 20) | ((unsigned)T2 << 10) | (unsigned)T3;
            for (int i = t; i < Na; i += 1024) {
                float v = g_bce[off + i];
                unsigned u = __float_as_uint(v);
                if ((int)u >= 0 && u > thrbits) sum += v;
            }
        }

        // block reduce sum
        s_fred[t] = sum;
        __syncthreads();
        #pragma unroll
        for (int s2 = 512; s2 > 0; s2 >>= 1) {
            if (t < s2) s_fred[t] += s_fred[t + s2];
            __syncthreads();
        }
        if (t == 0) {
            float neg_sum = s_fred[0] + (float)krf * __uint_as_float(thrbits);
            o = g_posbce[idx] / (float)npos + neg_sum / (float)k;
        }
    }

    if (t == 0) {
        float c = 0.f, l = 0.f;
        if (npos > 0) {
            c = g_cls[idx] / (float)npos;
            l = g_loc[idx] / (4.0f * (float)npos);
        }
        atomicAdd(&g_tot[0], o);
        atomicAdd(&g_tot[1], c);
        atomicAdd(&g_tot[2], l);
    }
}

__global__ void k_final(float* out) {
    if (threadIdx.x == 0) {
        float o = g_tot[0] / (float)NBATCH;
        float c = g_tot[1] / (float)NBATCH;
        float l = g_tot[2] / (float)NBATCH;
        out[0] = o; out[1] = c; out[2] = l; out[3] = o + c + l;
    }
}

extern "C" void kernel_launch(void* const* d_in, const int* in_sizes, int n_in,
                              void* d_out, int out_size)
{
    const float* p0 = (const float*)d_in[0];
    const float* p1 = (const float*)d_in[1];
    const float* p2 = (const float*)d_in[2];
    const float* a0 = (const float*)d_in[3];
    const float* a1 = (const float*)d_in[4];
    const float* a2 = (const float*)d_in[5];
    const float* tb = (const float*)d_in[6];
    const int*   tl = (const int*)  d_in[7];

    k_init<<<384, 1024>>>();
    dim3 gA(NB0 + NB1 + NB2, NBATCH);
    k_phaseA<<<gA, 256>>>(p0, p1, p2, a0, a1, a2, tb, tl);
    k_phaseB<<<192, 1024>>>();
    k_final<<<1, 32>>>((float*)d_out);
}